// round 2
// baseline (speedup 1.0000x reference)
#include <cuda_runtime.h>
#include <cstdint>
#include <cstddef>

// ===================== problem constants =====================
static constexpr int NP      = 50000;     // particles
static constexpr int NPAD    = 50048;     // padded to 391*128
static constexpr int EDG     = 800000;
static constexpr int CAP     = 64;        // slots per receiver (Poisson(16) tail-safe)
static constexpr int KDIM    = 512;       // folded contraction dim: 8 taps * 64 ch
static constexpr int OUTC    = 64;

// ===================== device scratch (no allocs allowed) =====================
__device__ int   g_deg[NPAD];
__device__ int4  g_slots[(size_t)NPAD * CAP];   // {sender, px, py, pad}
__device__ float g_A[(size_t)NPAD * KDIM];      // folded aggregate [NPAD, 512]
__device__ float g_Bhi[KDIM * OUTC];            // tf32-hi of folded kernel, [k][n]
__device__ float g_Blo[KDIM * OUTC];            // tf32-lo residual, [k][n]

// ===================== helpers =====================
__device__ __forceinline__ uint32_t f2tf32(float x) {
    uint32_t r;
    asm("cvt.rna.tf32.f32 %0, %1;" : "=r"(r) : "f"(x));
    return r;
}

__device__ __forceinline__ void mma8(float* c, const uint32_t* a, const uint32_t* b) {
    asm volatile(
        "mma.sync.aligned.m16n8k8.row.col.f32.tf32.tf32.f32 "
        "{%0,%1,%2,%3}, {%4,%5,%6,%7}, {%8,%9}, {%0,%1,%2,%3};"
        : "+f"(c[0]), "+f"(c[1]), "+f"(c[2]), "+f"(c[3])
        : "r"(a[0]), "r"(a[1]), "r"(a[2]), "r"(a[3]), "r"(b[0]), "r"(b[1]));
}

// ===================== kernel 1: zero degree counters =====================
__global__ void k_zero_deg() {
    int i = blockIdx.x * blockDim.x + threadIdx.x;
    if (i < NPAD) g_deg[i] = 0;
}

// ===================== kernel 2: bucket edges by receiver =====================
__global__ void k_fill(const int* __restrict__ recv, const int* __restrict__ snd,
                       const float* __restrict__ rp) {
    int e = blockIdx.x * blockDim.x + threadIdx.x;
    if (e >= EDG) return;
    int r = recv[e];
    int slot = atomicAdd(&g_deg[r], 1);
    if (slot < CAP) {
        g_slots[(size_t)r * CAP + slot] =
            make_int4(snd[e], __float_as_int(rp[2 * e]), __float_as_int(rp[2 * e + 1]), 0);
    }
}

// ===================== kernel 3: build folded B, tf32 hi/lo, [k][n] =====================
// folded tap t = x*4+y with x in {0,1}; k = t*64 + i
// y<2: kernel[x][y][i][n]; y in {2,3}: -kernel[3-x][3-y][i][n]
__global__ void k_buildB(const float* __restrict__ ker) {
    int idx = blockIdx.x * blockDim.x + threadIdx.x;
    if (idx >= KDIM * OUTC) return;
    int k = idx / OUTC;
    int n = idx % OUTC;
    int t = k / 64, i = k % 64;
    int x = t / 4, y = t % 4;
    float v;
    if (y < 2) v = ker[(((x * 2 + y) * 64 + i) * 64) + n];
    else       v = -ker[((((3 - x) * 2 + (3 - y)) * 64 + i) * 64) + n];
    uint32_t hb = f2tf32(v);
    float hi = __uint_as_float(hb);
    uint32_t lb = f2tf32(v - hi);
    g_Bhi[k * OUTC + n] = hi;
    g_Blo[k * OUTC + n] = __uint_as_float(lb);
}

// ===================== kernel 4: per-receiver folded aggregation =====================
// warp per receiver; smem Atil[8 taps][64 ch] fp32; lane handles channels (2l, 2l+1)
__global__ void __launch_bounds__(256) k_phase1(const float* __restrict__ feat,
                                                const float* __restrict__ ws_p) {
    __shared__ float sA[8][8 * 64];  // 8 warps * 2KB
    int warp = threadIdx.x >> 5, lane = threadIdx.x & 31;
    int r = blockIdx.x * 8 + warp;
    float* Aw = sA[warp];
    #pragma unroll
    for (int j = lane; j < 512; j += 32) Aw[j] = 0.f;
    __syncwarp();

    if (r < NPAD) {
        int nd = min(g_deg[r], CAP);
        float inv_ws = 1.0f / (*ws_p);
        const int4* slots = &g_slots[(size_t)r * CAP];
        for (int e = 0; e < nd; e++) {
            int4 s = slots[e];  // uniform across warp -> broadcast
            int   snd = s.x;
            float px = __int_as_float(s.y), py = __int_as_float(s.z);
            float ux = fminf(fmaxf(px * inv_ws, -1.f), 1.f);
            float uy = fminf(fmaxf(py * inv_ws, -1.f), 1.f);
            float gx = (ux + 1.f) * 1.5f;
            float gy = (uy + 1.f) * 1.5f;
            float x0 = fminf(fmaxf(floorf(gx), 0.f), 2.f);
            float y0 = fminf(fmaxf(floorf(gy), 0.f), 2.f);
            float fx = gx - x0, fy = gy - y0;
            int x0i = (int)x0, y0i = (int)y0;
            float r2 = ux * ux + uy * uy;
            float wn = fmaxf(1.f - r2, 0.f);
            wn = wn * wn * wn;
            float2 f2 = *(const float2*)(feat + (size_t)snd * 64 + lane * 2);
            float gv0 = f2.x * wn, gv1 = f2.y * wn;
            float wgt[4] = { (1.f - fx) * (1.f - fy), (1.f - fx) * fy,
                             fx * (1.f - fy),         fx * fy };
            int t0 = x0i * 4 + y0i;
            int taps[4] = { t0, t0 + 1, t0 + 4, t0 + 5 };
            #pragma unroll
            for (int c = 0; c < 4; c++) {
                int t = taps[c];
                float sg = 1.f;
                if (t >= 8) { t = 15 - t; sg = -1.f; }
                float wc = wgt[c] * sg;
                float2* p = (float2*)&Aw[t * 64 + lane * 2];
                float2 v = *p;
                v.x += wc * gv0;
                v.y += wc * gv1;
                *p = v;
            }
        }
    }
    __syncwarp();
    if (r < NPAD) {
        float4* dst = (float4*)(g_A + (size_t)r * KDIM);
        const float4* src = (const float4*)Aw;
        #pragma unroll
        for (int j = lane; j < 128; j += 32) dst[j] = src[j];
    }
}

// ===================== kernel 5: tf32 mma.sync GEMM with hi/lo split =====================
// out[NPAD(128/CTA), 64] = A[., 512] @ B[512, 64] + bias
// CTA: 256 thr = 8 warps as 4(M) x 2(N); warp: 32 rows x 32 cols = 2 mtiles x 4 ntiles
static constexpr int KC = 64;                 // K chunk
static constexpr int AST = 68;                // A smem row stride (floats) - conflict-free
static constexpr int BST = 72;                // B smem row stride (floats) - conflict-free
static constexpr int SM_AHI = 0;              // 128*68 = 8704 floats
static constexpr int SM_ALO = 8704;
static constexpr int SM_BHI = 17408;          // 64*72 = 4608 floats
static constexpr int SM_BLO = 22016;
static constexpr int GEMM_SMEM = 26624 * 4;   // 106496 bytes

__global__ void __launch_bounds__(256) k_gemm(const float* __restrict__ bias,
                                              float* __restrict__ out) {
    extern __shared__ float sm[];
    float* sAhi = sm + SM_AHI;
    float* sAlo = sm + SM_ALO;
    float* sBhi = sm + SM_BHI;
    float* sBlo = sm + SM_BLO;

    int tid = threadIdx.x;
    int warp = tid >> 5, lane = tid & 31;
    int gid = lane >> 2, tig = lane & 3;
    int warpM = warp >> 1, warpN = warp & 1;
    int m_base = warpM * 32;
    int n_base = warpN * 32;
    int m0 = blockIdx.x * 128;

    float acc[2][4][4];
    #pragma unroll
    for (int mt = 0; mt < 2; mt++)
        #pragma unroll
        for (int nt = 0; nt < 4; nt++)
            #pragma unroll
            for (int j = 0; j < 4; j++) acc[mt][nt][j] = 0.f;

    const float4* Ag  = (const float4*)g_A;
    const float4* Bhg = (const float4*)g_Bhi;
    const float4* Blg = (const float4*)g_Blo;

    for (int kc = 0; kc < KDIM / KC; kc++) {
        // ---- stage A chunk [128 x 64] with hi/lo split ----
        #pragma unroll
        for (int it = 0; it < 8; it++) {
            int idx = tid + it * 256;               // 0..2047 : 128 rows x 16 float4
            int row = idx >> 4, c4 = idx & 15;
            float4 v = Ag[(size_t)(m0 + row) * 128 + kc * 16 + c4];
            float4 hi, lo;
            {
                uint32_t h;
                h = f2tf32(v.x); hi.x = __uint_as_float(h); lo.x = __uint_as_float(f2tf32(v.x - hi.x));
                h = f2tf32(v.y); hi.y = __uint_as_float(h); lo.y = __uint_as_float(f2tf32(v.y - hi.y));
                h = f2tf32(v.z); hi.z = __uint_as_float(h); lo.z = __uint_as_float(f2tf32(v.z - hi.z));
                h = f2tf32(v.w); hi.w = __uint_as_float(h); lo.w = __uint_as_float(f2tf32(v.w - hi.w));
            }
            ((float4*)(sAhi + row * AST))[c4] = hi;
            ((float4*)(sAlo + row * AST))[c4] = lo;
        }
        // ---- stage B chunk [64 x 64] (pre-split in gmem) ----
        #pragma unroll
        for (int it = 0; it < 4; it++) {
            int idx = tid + it * 256;               // 0..1023 : 64 rows x 16 float4
            int row = idx >> 4, c4 = idx & 15;
            ((float4*)(sBhi + row * BST))[c4] = Bhg[(kc * 64 + row) * 16 + c4];
            ((float4*)(sBlo + row * BST))[c4] = Blg[(kc * 64 + row) * 16 + c4];
        }
        __syncthreads();

        // ---- 8 k-steps of m16n8k8 ----
        #pragma unroll
        for (int ks = 0; ks < 8; ks++) {
            int k0 = ks * 8;
            uint32_t ah[2][4], al[2][4], bh[4][2], bl[4][2];
            #pragma unroll
            for (int mt = 0; mt < 2; mt++) {
                int r0 = m_base + mt * 16 + gid;
                const float* ph = sAhi + r0 * AST + k0 + tig;
                const float* pl = sAlo + r0 * AST + k0 + tig;
                ah[mt][0] = __float_as_uint(ph[0]);
                ah[mt][1] = __float_as_uint(ph[8 * AST]);
                ah[mt][2] = __float_as_uint(ph[4]);
                ah[mt][3] = __float_as_uint(ph[8 * AST + 4]);
                al[mt][0] = __float_as_uint(pl[0]);
                al[mt][1] = __float_as_uint(pl[8 * AST]);
                al[mt][2] = __float_as_uint(pl[4]);
                al[mt][3] = __float_as_uint(pl[8 * AST + 4]);
            }
            #pragma unroll
            for (int nt = 0; nt < 4; nt++) {
                int col = n_base + nt * 8 + gid;
                const float* ph = sBhi + (k0 + tig) * BST + col;
                const float* pl = sBlo + (k0 + tig) * BST + col;
                bh[nt][0] = __float_as_uint(ph[0]);
                bh[nt][1] = __float_as_uint(ph[4 * BST]);
                bl[nt][0] = __float_as_uint(pl[0]);
                bl[nt][1] = __float_as_uint(pl[4 * BST]);
            }
            #pragma unroll
            for (int mt = 0; mt < 2; mt++)
                #pragma unroll
                for (int nt = 0; nt < 4; nt++) {
                    mma8(acc[mt][nt], ah[mt], bh[nt]);
                    mma8(acc[mt][nt], al[mt], bh[nt]);
                    mma8(acc[mt][nt], ah[mt], bl[nt]);
                }
        }
        __syncthreads();
    }

    // ---- epilogue: bias + store ----
    #pragma unroll
    for (int mt = 0; mt < 2; mt++) {
        int r  = m0 + m_base + mt * 16 + gid;
        int r8 = r + 8;
        #pragma unroll
        for (int nt = 0; nt < 4; nt++) {
            int c = n_base + nt * 8 + tig * 2;
            float b0 = __ldg(bias + c), b1 = __ldg(bias + c + 1);
            if (r < NP) {
                float2 v = make_float2(acc[mt][nt][0] + b0, acc[mt][nt][1] + b1);
                *(float2*)(out + (size_t)r * 64 + c) = v;
            }
            if (r8 < NP) {
                float2 v = make_float2(acc[mt][nt][2] + b0, acc[mt][nt][3] + b1);
                *(float2*)(out + (size_t)r8 * 64 + c) = v;
            }
        }
    }
}

// ===================== launch =====================
extern "C" void kernel_launch(void* const* d_in, const int* in_sizes, int n_in,
                              void* d_out, int out_size) {
    const float* feat = (const float*)d_in[0];
    const int*   recv = (const int*)d_in[1];
    const float* rp   = (const float*)d_in[2];
    const float* ws   = (const float*)d_in[3];
    const int*   snd  = (const int*)d_in[4];
    const float* ker  = (const float*)d_in[5];
    const float* bias = (const float*)d_in[6];
    float* out = (float*)d_out;

    cudaFuncSetAttribute(k_gemm, cudaFuncAttributeMaxDynamicSharedMemorySize, GEMM_SMEM);

    k_zero_deg<<<(NPAD + 255) / 256, 256>>>();
    k_fill<<<(EDG + 255) / 256, 256>>>(recv, snd, rp);
    k_buildB<<<(KDIM * OUTC + 255) / 256, 256>>>(ker);
    k_phase1<<<NPAD / 8, 256>>>(feat, ws);
    k_gemm<<<NPAD / 128, 128 * 2, GEMM_SMEM>>>(bias, out);
}